// round 11
// baseline (speedup 1.0000x reference)
#include <cuda_runtime.h>
#include <math.h>

// Problem constants
#define NX 256
#define NCH 3
#define NK 15
#define NPIX 65536
#define SIGMA_F 0.65f
#define MA_F 4.35f      // DD - SIGMA = 5 - 0.65
#define DT_F 0.2f

#define LPB 4           // FFT lines per block
#define FFT_THREADS (LPB * 128)

// Scratch (static device arrays: no allocation allowed)
__device__ float2 d_fA[NCH * NPIX];   // per-channel FFT of A, layout [c][x][y]
__device__ float2 d_Gc[NK * NPIX];    // per-kernel spectra / row-IFFT intermediates [k][x][y]
__device__ float  d_Ug[NK * NPIX];    // growth(U)*P per kernel [k][x][y]
__device__ float  d_Uc[NCH * NPIX];   // channel-summed U [c][x][y]
__device__ float  d_Asum[NPIX];
__device__ float  d_mus[6 * NPIX];    // per cell: [d*3 + c], d in {0,1}

// ---------------------------------------------------------------------------
// Shared twiddle table: tw[t] = (cos, sin)(sign * 2*pi * t / 256), t in [0,128).
// Bit-exact replacement for per-stage sincosf: at stage `len`, the angle
// sign*2pi*j/len equals sign*2pi*(j<<(8-log2 len))/256 with identical fp32
// rounding (operands differ only by powers of two).
// ---------------------------------------------------------------------------
__device__ __forceinline__ void fill_twiddles(float2* tw, int btid, int nthreads, float sign) {
    for (int t = btid; t < 128; t += nthreads) {
        float ang = sign * 6.283185307179586f * (float)t / 256.f;
        float wr, wi;
        sincosf(ang, &wi, &wr);
        tw[t] = make_float2(wr, wi);
    }
}

// ---------------------------------------------------------------------------
// 256-point in-shared-memory radix-2 DIT FFT, 128 threads per line.
// All lines in the block run the same stage sequence, so the block-wide
// __syncthreads() are uniform across the batched lines.
// ---------------------------------------------------------------------------
__device__ __forceinline__ void fft256(float2* s, const float2* __restrict__ tw, int tid) {
    for (int i = tid; i < 256; i += 128) {
        int j = __brev((unsigned)i) >> 24;
        if (i < j) { float2 t = s[i]; s[i] = s[j]; s[j] = t; }
    }
    __syncthreads();
    #pragma unroll
    for (int p = 1; p <= 8; p++) {
        int len = 1 << p;
        int half = len >> 1;
        int g = tid >> (p - 1);
        int j = tid & (half - 1);
        int base = g * len + j;
        float2 w = tw[j << (8 - p)];
        float2 u = s[base];
        float2 v = s[base + half];
        float vr = v.x * w.x - v.y * w.y;
        float vi = v.x * w.y + v.y * w.x;
        s[base]        = make_float2(u.x + vr, u.y + vi);
        s[base + half] = make_float2(u.x - vr, u.y - vi);
        __syncthreads();
    }
}

// ---------------------------------------------------------------------------
// Forward FFT of A: rows (axis 1) then columns (axis 0).
// grid.x spans line-groups of LPB, grid.y = channel.
// ---------------------------------------------------------------------------
__global__ void __launch_bounds__(FFT_THREADS) k_fwd_rows(const float* __restrict__ A) {
    __shared__ float2 s[LPB][256];
    __shared__ float2 tw[128];
    fill_twiddles(tw, threadIdx.x, FFT_THREADS, -1.f);
    int lane = threadIdx.x & 127;
    int line = threadIdx.x >> 7;
    int x = blockIdx.x * LPB + line;
    int c = blockIdx.y;
    float2* sl = s[line];
    for (int y = lane; y < 256; y += 128)
        sl[y] = make_float2(A[(x * 256 + y) * NCH + c], 0.f);
    __syncthreads();
    fft256(sl, tw, lane);
    float2* out = d_fA + c * NPIX + x * 256;
    for (int y = lane; y < 256; y += 128) out[y] = sl[y];
}

__global__ void __launch_bounds__(FFT_THREADS) k_fwd_cols() {
    __shared__ float2 s[LPB][256];
    __shared__ float2 tw[128];
    fill_twiddles(tw, threadIdx.x, FFT_THREADS, -1.f);
    int lane = threadIdx.x & 127;
    int line = threadIdx.x >> 7;
    int y = blockIdx.x * LPB + line;
    int c = blockIdx.y;
    float2* sl = s[line];
    float2* base = d_fA + c * NPIX + y;
    for (int x = lane; x < 256; x += 128) sl[x] = base[x * 256];
    __syncthreads();
    fft256(sl, tw, lane);
    for (int x = lane; x < 256; x += 128) base[x * 256] = sl[x];
}

// ---------------------------------------------------------------------------
// Pointwise fK * fA[k%3], then inverse FFT rows (axis 1)
// ---------------------------------------------------------------------------
__global__ void __launch_bounds__(FFT_THREADS) k_inv_rows(const float* __restrict__ fKr,
                                                          const float* __restrict__ fKi) {
    __shared__ float2 s[LPB][256];
    __shared__ float2 tw[128];
    fill_twiddles(tw, threadIdx.x, FFT_THREADS, 1.f);
    int lane = threadIdx.x & 127;
    int line = threadIdx.x >> 7;
    int x = blockIdx.x * LPB + line;
    int k = blockIdx.y;
    int c = k % NCH;
    float2* sl = s[line];
    for (int y = lane; y < 256; y += 128) {
        float2 a = d_fA[c * NPIX + x * 256 + y];
        int fi = (x * 256 + y) * NK + k;
        float kr = __ldg(&fKr[fi]), ki = __ldg(&fKi[fi]);
        sl[y] = make_float2(kr * a.x - ki * a.y, kr * a.y + ki * a.x);
    }
    __syncthreads();
    fft256(sl, tw, lane);
    float2* out = d_Gc + k * NPIX + x * 256;
    for (int y = lane; y < 256; y += 128) out[y] = sl[y];
}

// Inverse FFT columns (axis 0) + growth function * P
__global__ void __launch_bounds__(FFT_THREADS) k_inv_cols(const float* __restrict__ P,
                                                          const float* __restrict__ mArr,
                                                          const float* __restrict__ sArr) {
    __shared__ float2 s[LPB][256];
    __shared__ float2 tw[128];
    fill_twiddles(tw, threadIdx.x, FFT_THREADS, 1.f);
    int lane = threadIdx.x & 127;
    int line = threadIdx.x >> 7;
    int y = blockIdx.x * LPB + line;
    int k = blockIdx.y;
    float2* sl = s[line];
    float2* base = d_Gc + k * NPIX + y;
    for (int x = lane; x < 256; x += 128) sl[x] = base[x * 256];
    __syncthreads();
    fft256(sl, tw, lane);
    float mk = mArr[k];
    float sk = sArr[k];
    float inv2s2 = 1.f / (2.f * sk * sk);
    for (int x = lane; x < 256; x += 128) {
        float u = sl[x].x * (1.f / 65536.f);
        float d = u - mk;
        float g = 2.f * expf(-d * d * inv2s2) - 1.f;
        d_Ug[k * NPIX + x * 256 + y] = g * P[(x * 256 + y) * NK + k];
    }
}

// ---------------------------------------------------------------------------
// Channel sum: Uc[c] = sum_{k%3==c} Ug[k]; Asum = sum_c A
// ---------------------------------------------------------------------------
__global__ void __launch_bounds__(256) k_chan(const float* __restrict__ A) {
    int idx = blockIdx.x * 256 + threadIdx.x;
    #pragma unroll
    for (int c = 0; c < NCH; c++) {
        float sum = 0.f;
        #pragma unroll
        for (int j = 0; j < 5; j++) sum += d_Ug[(c + 3 * j) * NPIX + idx];
        d_Uc[c * NPIX + idx] = sum;
    }
    d_Asum[idx] = A[idx * 3] + A[idx * 3 + 1] + A[idx * 3 + 2];
}

// ---------------------------------------------------------------------------
// Sobel (true convolution, zero-padded 'same'), per plane
// ---------------------------------------------------------------------------
__device__ __forceinline__ void sobel_at(const float* __restrict__ p, int x, int y,
                                         float& g0, float& g1) {
    float v[3][3];
    #pragma unroll
    for (int i = -1; i <= 1; i++) {
        #pragma unroll
        for (int j = -1; j <= 1; j++) {
            int xx = x + i, yy = y + j;
            bool ok = (xx >= 0) && (xx < 256) && (yy >= 0) && (yy < 256);
            v[i + 1][j + 1] = ok ? p[xx * 256 + yy] : 0.f;
        }
    }
    g0 = (v[2][0] + 2.f * v[2][1] + v[2][2]) - (v[0][0] + 2.f * v[0][1] + v[0][2]);
    g1 = (v[0][2] + 2.f * v[1][2] + v[2][2]) - (v[0][0] + 2.f * v[1][0] + v[2][0]);
}

// Flow field + target centers (mus)
__global__ void __launch_bounds__(256) k_flow(const float* __restrict__ A) {
    int idx = blockIdx.x * 256 + threadIdx.x;
    int x = idx >> 8, y = idx & 255;
    float cg0, cg1;
    sobel_at(d_Asum, x, y, cg0, cg1);
    #pragma unroll
    for (int c = 0; c < NCH; c++) {
        float g0, g1;
        sobel_at(d_Uc + c * NPIX, x, y, g0, g1);
        float a = A[idx * 3 + c] * 0.5f;
        float alpha = fminf(a * a, 1.f);
        float F0 = fminf(fmaxf(g0 * (1.f - alpha) - cg0 * alpha, -MA_F), MA_F);
        float F1 = fminf(fmaxf(g1 * (1.f - alpha) - cg1 * alpha, -MA_F), MA_F);
        float mu0 = fminf(fmaxf((float)x + 0.5f + DT_F * F0, SIGMA_F), 256.f - SIGMA_F);
        float mu1 = fminf(fmaxf((float)y + 0.5f + DT_F * F1, SIGMA_F), 256.f - SIGMA_F);
        d_mus[idx * 6 + c]     = mu0;  // d = 0 (axis 0)
        d_mus[idx * 6 + 3 + c] = mu1;  // d = 1 (axis 1)
    }
}

// ---------------------------------------------------------------------------
// Reintegration gather. Only shifts |dx|,|dy| <= 2 can be nonzero:
// |mus - pos_src| <= DT*MA = 0.87 (wall clip preserves this), so
// dpmu >= |dx| - 0.87 >= 2.13 > 0.5+SIGMA for |dx| >= 3 => area == 0 =>
// e = exp(0)-1 == 0 exactly (identical to reference's 121-shift sum).
// ---------------------------------------------------------------------------
__global__ void __launch_bounds__(256) k_reint(const float* __restrict__ A,
                                               const float* __restrict__ P,
                                               float* __restrict__ out) {
    int idx = blockIdx.x * 256 + threadIdx.x;
    int x = idx >> 8, y = idx & 255;
    float px = (float)x + 0.5f, py = (float)y + 0.5f;
    const float invN = 1.f / (4.f * SIGMA_F * SIGMA_F);

    float nA0 = 0.f, nA1 = 0.f, nA2 = 0.f;
    float accP[NK];
    #pragma unroll
    for (int k = 0; k < NK; k++) accP[k] = 0.f;
    float wsum = 0.f;

    for (int dx = -2; dx <= 2; dx++) {
        int sx = (x - dx) & 255;
        for (int dy = -2; dy <= 2; dy++) {
            int sy = (y - dy) & 255;
            int sidx = sx * 256 + sy;
            const float* mu = d_mus + sidx * 6;

            float c0, c1, c2;
            {
                float f0 = fminf(fmaxf(0.5f + SIGMA_F - fabsf(px - __ldg(&mu[0])), 0.f), 1.f);
                float f1 = fminf(fmaxf(0.5f + SIGMA_F - fabsf(py - __ldg(&mu[3])), 0.f), 1.f);
                c0 = __ldg(&A[sidx * 3 + 0]) * (f0 * f1 * invN);
            }
            {
                float f0 = fminf(fmaxf(0.5f + SIGMA_F - fabsf(px - __ldg(&mu[1])), 0.f), 1.f);
                float f1 = fminf(fmaxf(0.5f + SIGMA_F - fabsf(py - __ldg(&mu[4])), 0.f), 1.f);
                c1 = __ldg(&A[sidx * 3 + 1]) * (f0 * f1 * invN);
            }
            {
                float f0 = fminf(fmaxf(0.5f + SIGMA_F - fabsf(px - __ldg(&mu[2])), 0.f), 1.f);
                float f1 = fminf(fmaxf(0.5f + SIGMA_F - fabsf(py - __ldg(&mu[5])), 0.f), 1.f);
                c2 = __ldg(&A[sidx * 3 + 2]) * (f0 * f1 * invN);
            }
            float s = c0 + c1 + c2;
            nA0 += c0; nA1 += c1; nA2 += c2;
            float e = expf(s) - 1.f;
            wsum += e;
            if (s != 0.f) {
                const float* Ps = P + sidx * NK;
                #pragma unroll
                for (int k = 0; k < NK; k++) accP[k] += __ldg(&Ps[k]) * e;
            }
        }
    }

    out[idx * 3 + 0] = nA0;
    out[idx * 3 + 1] = nA1;
    out[idx * 3 + 2] = nA2;
    float inv = 1.f / (wsum + 1e-10f);
    float* outP = out + NPIX * 3;
    #pragma unroll
    for (int k = 0; k < NK; k++) outP[idx * NK + k] = accP[k] * inv;
}

// ---------------------------------------------------------------------------
extern "C" void kernel_launch(void* const* d_in, const int* in_sizes, int n_in,
                              void* d_out, int out_size) {
    (void)in_sizes; (void)n_in; (void)out_size;
    const float* A   = (const float*)d_in[0];
    const float* P   = (const float*)d_in[1];
    const float* fKr = (const float*)d_in[2];
    const float* fKi = (const float*)d_in[3];
    const float* m   = (const float*)d_in[4];
    const float* s   = (const float*)d_in[5];
    float* out = (float*)d_out;

    k_fwd_rows<<<dim3(256 / LPB, NCH), FFT_THREADS>>>(A);
    k_fwd_cols<<<dim3(256 / LPB, NCH), FFT_THREADS>>>();
    k_inv_rows<<<dim3(256 / LPB, NK), FFT_THREADS>>>(fKr, fKi);
    k_inv_cols<<<dim3(256 / LPB, NK), FFT_THREADS>>>(P, m, s);
    k_chan<<<256, 256>>>(A);
    k_flow<<<256, 256>>>(A);
    k_reint<<<256, 256>>>(A, P, out);
}

// round 13
// speedup vs baseline: 1.0734x; 1.0734x over previous
#include <cuda_runtime.h>
#include <math.h>

// Problem constants
#define NCH 3
#define NK 15
#define NPIX 65536
#define SIGMA_F 0.65f
#define MA_F 4.35f      // DD - SIGMA = 5 - 0.65
#define DT_F 0.2f

#define LPB 4           // FFT lines per block (row kernels)
#define FFT_THREADS (LPB * 128)
#define TW 16           // columns per tile (column kernels)
#define CSTRIDE 257     // padded column line stride (float2) -> conflict-free transpose

// Scratch (static device arrays: no allocation allowed)
__device__ float2 d_fA[NCH * NPIX];   // per-channel FFT of A, layout [c][x][y]
__device__ float2 d_Gc[NK * NPIX];    // per-kernel spectra / row-IFFT intermediates [k][x][y]
__device__ float2 d_fKT[NK * NPIX];   // transposed kernel FFT [k][x][y]
__device__ float  d_Ug[NK * NPIX];    // RAW ifft2 real part (unscaled) per kernel [k][x][y]
__device__ float  d_Uc[NCH * NPIX];   // channel-summed growth*P [c][x][y]
__device__ float  d_Asum[NPIX];
__device__ float  d_mus[6 * NPIX];    // per cell: [d*3 + c], d in {0,1}

// ---------------------------------------------------------------------------
// Shared twiddle table (bit-exact vs per-stage sincosf; see R6 note)
// ---------------------------------------------------------------------------
__device__ __forceinline__ void fill_twiddles(float2* tw, int btid, int nthreads, float sign) {
    for (int t = btid; t < 128; t += nthreads) {
        float ang = sign * 6.283185307179586f * (float)t / 256.f;
        float wr, wi;
        sincosf(ang, &wi, &wr);
        tw[t] = make_float2(wr, wi);
    }
}

// ---------------------------------------------------------------------------
// 256-point smem radix-2 DIT FFT, 128 threads per line. Block-uniform barriers.
// ---------------------------------------------------------------------------
__device__ __forceinline__ void fft256(float2* s, const float2* __restrict__ tw, int tid) {
    for (int i = tid; i < 256; i += 128) {
        int j = __brev((unsigned)i) >> 24;
        if (i < j) { float2 t = s[i]; s[i] = s[j]; s[j] = t; }
    }
    __syncthreads();
    #pragma unroll
    for (int p = 1; p <= 8; p++) {
        int len = 1 << p;
        int half = len >> 1;
        int g = tid >> (p - 1);
        int j = tid & (half - 1);
        int base = g * len + j;
        float2 w = tw[j << (8 - p)];
        float2 u = s[base];
        float2 v = s[base + half];
        float vr = v.x * w.x - v.y * w.y;
        float vi = v.x * w.y + v.y * w.x;
        s[base]        = make_float2(u.x + vr, u.y + vi);
        s[base + half] = make_float2(u.x - vr, u.y - vi);
        __syncthreads();
    }
}

// ---------------------------------------------------------------------------
// fK transpose: [pix][k] interleaved -> [k][pix] planes (coalesced both sides)
// ---------------------------------------------------------------------------
__global__ void __launch_bounds__(256) k_tK(const float* __restrict__ fKr,
                                            const float* __restrict__ fKi) {
    int idx = blockIdx.x * 256 + threadIdx.x;
    #pragma unroll
    for (int k = 0; k < NK; k++)
        d_fKT[k * NPIX + idx] = make_float2(__ldg(&fKr[idx * NK + k]),
                                            __ldg(&fKi[idx * NK + k]));
}

// ---------------------------------------------------------------------------
// Forward FFT rows (axis 1): coalesced already. grid=(64, 3), 512 thr.
// ---------------------------------------------------------------------------
__global__ void __launch_bounds__(FFT_THREADS) k_fwd_rows(const float* __restrict__ A) {
    __shared__ float2 s[LPB][256];
    __shared__ float2 tw[128];
    fill_twiddles(tw, threadIdx.x, FFT_THREADS, -1.f);
    int lane = threadIdx.x & 127;
    int line = threadIdx.x >> 7;
    int x = blockIdx.x * LPB + line;
    int c = blockIdx.y;
    float2* sl = s[line];
    for (int y = lane; y < 256; y += 128)
        sl[y] = make_float2(A[(x * 256 + y) * NCH + c], 0.f);
    __syncthreads();
    fft256(sl, tw, lane);
    float2* out = d_fA + c * NPIX + x * 256;
    for (int y = lane; y < 256; y += 128) out[y] = sl[y];
}

// ---------------------------------------------------------------------------
// Forward FFT columns, 16-col tile, coalesced global I/O via padded smem
// transpose. grid=(16, 3), 512 thr.
// ---------------------------------------------------------------------------
__global__ void __launch_bounds__(512) k_fwd_cols() {
    __shared__ float2 sc[TW * CSTRIDE];
    __shared__ float2 tw[128];
    fill_twiddles(tw, threadIdx.x, 512, -1.f);
    int t = threadIdx.x;
    int y0 = blockIdx.x * TW;
    float2* plane = d_fA + blockIdx.y * NPIX;
    #pragma unroll
    for (int i = 0; i < 8; i++) {
        int row = i * 32 + (t >> 4);
        int col = t & 15;
        sc[col * CSTRIDE + row] = plane[row * 256 + y0 + col];
    }
    __syncthreads();
    int lane = t & 127, grp = t >> 7;
    for (int j = 0; j < 4; j++)
        fft256(sc + (j * 4 + grp) * CSTRIDE, tw, lane);
    __syncthreads();
    #pragma unroll
    for (int i = 0; i < 8; i++) {
        int row = i * 32 + (t >> 4);
        int col = t & 15;
        plane[row * 256 + y0 + col] = sc[col * CSTRIDE + row];
    }
}

// ---------------------------------------------------------------------------
// Pointwise fKT * fA[k%3], then inverse FFT rows. grid=(64, 15), 512 thr.
// ---------------------------------------------------------------------------
__global__ void __launch_bounds__(FFT_THREADS) k_inv_rows() {
    __shared__ float2 s[LPB][256];
    __shared__ float2 tw[128];
    fill_twiddles(tw, threadIdx.x, FFT_THREADS, 1.f);
    int lane = threadIdx.x & 127;
    int line = threadIdx.x >> 7;
    int x = blockIdx.x * LPB + line;
    int k = blockIdx.y;
    int c = k % NCH;
    float2* sl = s[line];
    for (int y = lane; y < 256; y += 128) {
        float2 a  = d_fA[c * NPIX + x * 256 + y];
        float2 kk = d_fKT[k * NPIX + x * 256 + y];
        sl[y] = make_float2(kk.x * a.x - kk.y * a.y, kk.x * a.y + kk.y * a.x);
    }
    __syncthreads();
    fft256(sl, tw, lane);
    float2* out = d_Gc + k * NPIX + x * 256;
    for (int y = lane; y < 256; y += 128) out[y] = sl[y];
}

// ---------------------------------------------------------------------------
// Inverse FFT columns, 16-col tile, coalesced; stores RAW real part only.
// grid=(16, 15), 512 thr.
// ---------------------------------------------------------------------------
__global__ void __launch_bounds__(512) k_inv_cols() {
    __shared__ float2 sc[TW * CSTRIDE];
    __shared__ float2 tw[128];
    fill_twiddles(tw, threadIdx.x, 512, 1.f);
    int t = threadIdx.x;
    int y0 = blockIdx.x * TW;
    int k = blockIdx.y;
    float2* plane = d_Gc + k * NPIX;
    #pragma unroll
    for (int i = 0; i < 8; i++) {
        int row = i * 32 + (t >> 4);
        int col = t & 15;
        sc[col * CSTRIDE + row] = plane[row * 256 + y0 + col];
    }
    __syncthreads();
    int lane = t & 127, grp = t >> 7;
    for (int j = 0; j < 4; j++)
        fft256(sc + (j * 4 + grp) * CSTRIDE, tw, lane);
    __syncthreads();
    float* uplane = d_Ug + k * NPIX;
    #pragma unroll
    for (int i = 0; i < 8; i++) {
        int row = i * 32 + (t >> 4);
        int col = t & 15;
        uplane[row * 256 + y0 + col] = sc[col * CSTRIDE + row].x;
    }
}

// ---------------------------------------------------------------------------
// growth(U)*P + channel sum + Asum, all coalesced per pixel.
// Op order identical to the R11 k_inv_cols epilogue + k_chan => bit-exact.
// ---------------------------------------------------------------------------
__global__ void __launch_bounds__(256) k_growchan(const float* __restrict__ A,
                                                  const float* __restrict__ P,
                                                  const float* __restrict__ mArr,
                                                  const float* __restrict__ sArr) {
    __shared__ float sm[NK], sinv[NK];
    if (threadIdx.x < NK) {
        float sk = sArr[threadIdx.x];
        sm[threadIdx.x]   = mArr[threadIdx.x];
        sinv[threadIdx.x] = 1.f / (2.f * sk * sk);
    }
    __syncthreads();
    int idx = blockIdx.x * 256 + threadIdx.x;
    float uc0 = 0.f, uc1 = 0.f, uc2 = 0.f;
    #pragma unroll
    for (int j = 0; j < 5; j++) {
        #pragma unroll
        for (int c = 0; c < NCH; c++) {
            int k = c + 3 * j;                 // same accumulation order as old k_chan
            float u = d_Ug[k * NPIX + idx] * (1.f / 65536.f);
            float d = u - sm[k];
            float g = 2.f * expf(-d * d * sinv[k]) - 1.f;
            float v = g * __ldg(&P[idx * NK + k]);
            if (c == 0) uc0 += v; else if (c == 1) uc1 += v; else uc2 += v;
        }
    }
    d_Uc[0 * NPIX + idx] = uc0;
    d_Uc[1 * NPIX + idx] = uc1;
    d_Uc[2 * NPIX + idx] = uc2;
    d_Asum[idx] = A[idx * 3] + A[idx * 3 + 1] + A[idx * 3 + 2];
}

// ---------------------------------------------------------------------------
// Sobel (true convolution, zero-padded 'same'), per plane
// ---------------------------------------------------------------------------
__device__ __forceinline__ void sobel_at(const float* __restrict__ p, int x, int y,
                                         float& g0, float& g1) {
    float v[3][3];
    #pragma unroll
    for (int i = -1; i <= 1; i++) {
        #pragma unroll
        for (int j = -1; j <= 1; j++) {
            int xx = x + i, yy = y + j;
            bool ok = (xx >= 0) && (xx < 256) && (yy >= 0) && (yy < 256);
            v[i + 1][j + 1] = ok ? p[xx * 256 + yy] : 0.f;
        }
    }
    g0 = (v[2][0] + 2.f * v[2][1] + v[2][2]) - (v[0][0] + 2.f * v[0][1] + v[0][2]);
    g1 = (v[0][2] + 2.f * v[1][2] + v[2][2]) - (v[0][0] + 2.f * v[1][0] + v[2][0]);
}

// Flow field + target centers (mus)
__global__ void __launch_bounds__(256) k_flow(const float* __restrict__ A) {
    int idx = blockIdx.x * 256 + threadIdx.x;
    int x = idx >> 8, y = idx & 255;
    float cg0, cg1;
    sobel_at(d_Asum, x, y, cg0, cg1);
    #pragma unroll
    for (int c = 0; c < NCH; c++) {
        float g0, g1;
        sobel_at(d_Uc + c * NPIX, x, y, g0, g1);
        float a = A[idx * 3 + c] * 0.5f;
        float alpha = fminf(a * a, 1.f);
        float F0 = fminf(fmaxf(g0 * (1.f - alpha) - cg0 * alpha, -MA_F), MA_F);
        float F1 = fminf(fmaxf(g1 * (1.f - alpha) - cg1 * alpha, -MA_F), MA_F);
        float mu0 = fminf(fmaxf((float)x + 0.5f + DT_F * F0, SIGMA_F), 256.f - SIGMA_F);
        float mu1 = fminf(fmaxf((float)y + 0.5f + DT_F * F1, SIGMA_F), 256.f - SIGMA_F);
        d_mus[idx * 6 + c]     = mu0;  // d = 0 (axis 0)
        d_mus[idx * 6 + 3 + c] = mu1;  // d = 1 (axis 1)
    }
}

// ---------------------------------------------------------------------------
// Reintegration gather (25-shift exact truncation; see prior rounds)
// ---------------------------------------------------------------------------
__global__ void __launch_bounds__(256) k_reint(const float* __restrict__ A,
                                               const float* __restrict__ P,
                                               float* __restrict__ out) {
    int idx = blockIdx.x * 256 + threadIdx.x;
    int x = idx >> 8, y = idx & 255;
    float px = (float)x + 0.5f, py = (float)y + 0.5f;
    const float invN = 1.f / (4.f * SIGMA_F * SIGMA_F);

    float nA0 = 0.f, nA1 = 0.f, nA2 = 0.f;
    float accP[NK];
    #pragma unroll
    for (int k = 0; k < NK; k++) accP[k] = 0.f;
    float wsum = 0.f;

    for (int dx = -2; dx <= 2; dx++) {
        int sx = (x - dx) & 255;
        for (int dy = -2; dy <= 2; dy++) {
            int sy = (y - dy) & 255;
            int sidx = sx * 256 + sy;
            const float* mu = d_mus + sidx * 6;

            float c0, c1, c2;
            {
                float f0 = fminf(fmaxf(0.5f + SIGMA_F - fabsf(px - __ldg(&mu[0])), 0.f), 1.f);
                float f1 = fminf(fmaxf(0.5f + SIGMA_F - fabsf(py - __ldg(&mu[3])), 0.f), 1.f);
                c0 = __ldg(&A[sidx * 3 + 0]) * (f0 * f1 * invN);
            }
            {
                float f0 = fminf(fmaxf(0.5f + SIGMA_F - fabsf(px - __ldg(&mu[1])), 0.f), 1.f);
                float f1 = fminf(fmaxf(0.5f + SIGMA_F - fabsf(py - __ldg(&mu[4])), 0.f), 1.f);
                c1 = __ldg(&A[sidx * 3 + 1]) * (f0 * f1 * invN);
            }
            {
                float f0 = fminf(fmaxf(0.5f + SIGMA_F - fabsf(px - __ldg(&mu[2])), 0.f), 1.f);
                float f1 = fminf(fmaxf(0.5f + SIGMA_F - fabsf(py - __ldg(&mu[5])), 0.f), 1.f);
                c2 = __ldg(&A[sidx * 3 + 2]) * (f0 * f1 * invN);
            }
            float s = c0 + c1 + c2;
            nA0 += c0; nA1 += c1; nA2 += c2;
            float e = expf(s) - 1.f;
            wsum += e;
            if (s != 0.f) {
                const float* Ps = P + sidx * NK;
                #pragma unroll
                for (int k = 0; k < NK; k++) accP[k] += __ldg(&Ps[k]) * e;
            }
        }
    }

    out[idx * 3 + 0] = nA0;
    out[idx * 3 + 1] = nA1;
    out[idx * 3 + 2] = nA2;
    float inv = 1.f / (wsum + 1e-10f);
    float* outP = out + NPIX * 3;
    #pragma unroll
    for (int k = 0; k < NK; k++) outP[idx * NK + k] = accP[k] * inv;
}

// ---------------------------------------------------------------------------
extern "C" void kernel_launch(void* const* d_in, const int* in_sizes, int n_in,
                              void* d_out, int out_size) {
    (void)in_sizes; (void)n_in; (void)out_size;
    const float* A   = (const float*)d_in[0];
    const float* P   = (const float*)d_in[1];
    const float* fKr = (const float*)d_in[2];
    const float* fKi = (const float*)d_in[3];
    const float* m   = (const float*)d_in[4];
    const float* s   = (const float*)d_in[5];
    float* out = (float*)d_out;

    k_tK<<<256, 256>>>(fKr, fKi);
    k_fwd_rows<<<dim3(256 / LPB, NCH), FFT_THREADS>>>(A);
    k_fwd_cols<<<dim3(256 / TW, NCH), 512>>>();
    k_inv_rows<<<dim3(256 / LPB, NK), FFT_THREADS>>>();
    k_inv_cols<<<dim3(256 / TW, NK), 512>>>();
    k_growchan<<<256, 256>>>(A, P, m, s);
    k_flow<<<256, 256>>>(A);
    k_reint<<<256, 256>>>(A, P, out);
}

// round 17
// speedup vs baseline: 1.2562x; 1.1703x over previous
#include <cuda_runtime.h>
#include <math.h>

// Problem constants
#define NCH 3
#define NK 15
#define NPAIR 8         // 7 pairs + 1 single inverse transform
#define NPIX 65536
#define SIGMA_F 0.65f
#define MA_F 4.35f      // DD - SIGMA = 5 - 0.65
#define DT_F 0.2f

#define LPB 4           // FFT lines per block (row kernels)
#define FFT_THREADS (LPB * 128)
#define TW 16           // columns per tile (column kernels)
#define CSTRIDE 257     // padded column line stride (float2) -> conflict-free transpose

// Scratch (static device arrays: no allocation allowed)
__device__ float2 d_fA[NCH * NPIX];    // per-channel FFT of A, layout [c][x][y]
__device__ float2 d_Gc[NPAIR * NPIX];  // paired spectra / row-IFFT intermediates [p][x][y]
__device__ float2 d_fKT[NK * NPIX];    // transposed kernel FFT [k][x][y]
__device__ float  d_Ug[NK * NPIX];     // RAW ifft2 real part (unscaled) per kernel [k][x][y]
__device__ float  d_Uc[NCH * NPIX];    // channel-summed growth*P [c][x][y]
__device__ float  d_Asum[NPIX];
__device__ float  d_mus[6 * NPIX];     // per cell: [d*3 + c], d in {0,1}

// ---------------------------------------------------------------------------
// Shared twiddle table (bit-exact vs per-stage sincosf; see R6 note)
// ---------------------------------------------------------------------------
__device__ __forceinline__ void fill_twiddles(float2* tw, int btid, int nthreads, float sign) {
    for (int t = btid; t < 128; t += nthreads) {
        float ang = sign * 6.283185307179586f * (float)t / 256.f;
        float wr, wi;
        sincosf(ang, &wi, &wr);
        tw[t] = make_float2(wr, wi);
    }
}

// ---------------------------------------------------------------------------
// 256-point smem radix-2 DIT FFT, 128 threads per line. Block-uniform barriers.
// ---------------------------------------------------------------------------
__device__ __forceinline__ void fft256(float2* s, const float2* __restrict__ tw, int tid) {
    for (int i = tid; i < 256; i += 128) {
        int j = __brev((unsigned)i) >> 24;
        if (i < j) { float2 t = s[i]; s[i] = s[j]; s[j] = t; }
    }
    __syncthreads();
    #pragma unroll
    for (int p = 1; p <= 8; p++) {
        int len = 1 << p;
        int half = len >> 1;
        int g = tid >> (p - 1);
        int j = tid & (half - 1);
        int base = g * len + j;
        float2 w = tw[j << (8 - p)];
        float2 u = s[base];
        float2 v = s[base + half];
        float vr = v.x * w.x - v.y * w.y;
        float vi = v.x * w.y + v.y * w.x;
        s[base]        = make_float2(u.x + vr, u.y + vi);
        s[base + half] = make_float2(u.x - vr, u.y - vi);
        __syncthreads();
    }
}

// ---------------------------------------------------------------------------
// fK transpose: [pix][k] interleaved -> [k][pix] planes (coalesced both sides)
// ---------------------------------------------------------------------------
__global__ void __launch_bounds__(256) k_tK(const float* __restrict__ fKr,
                                            const float* __restrict__ fKi) {
    int idx = blockIdx.x * 256 + threadIdx.x;
    #pragma unroll
    for (int k = 0; k < NK; k++)
        d_fKT[k * NPIX + idx] = make_float2(__ldg(&fKr[idx * NK + k]),
                                            __ldg(&fKi[idx * NK + k]));
}

// ---------------------------------------------------------------------------
// Forward FFT rows (axis 1). grid=(64, 3), 512 thr.
// ---------------------------------------------------------------------------
__global__ void __launch_bounds__(FFT_THREADS) k_fwd_rows(const float* __restrict__ A) {
    __shared__ float2 s[LPB][256];
    __shared__ float2 tw[128];
    fill_twiddles(tw, threadIdx.x, FFT_THREADS, -1.f);
    int lane = threadIdx.x & 127;
    int line = threadIdx.x >> 7;
    int x = blockIdx.x * LPB + line;
    int c = blockIdx.y;
    float2* sl = s[line];
    for (int y = lane; y < 256; y += 128)
        sl[y] = make_float2(A[(x * 256 + y) * NCH + c], 0.f);
    __syncthreads();
    fft256(sl, tw, lane);
    float2* out = d_fA + c * NPIX + x * 256;
    for (int y = lane; y < 256; y += 128) out[y] = sl[y];
}

// ---------------------------------------------------------------------------
// Forward FFT columns, 16-col tile, coalesced via padded smem. grid=(16,3).
// ---------------------------------------------------------------------------
__global__ void __launch_bounds__(512) k_fwd_cols() {
    __shared__ float2 sc[TW * CSTRIDE];
    __shared__ float2 tw[128];
    fill_twiddles(tw, threadIdx.x, 512, -1.f);
    int t = threadIdx.x;
    int y0 = blockIdx.x * TW;
    float2* plane = d_fA + blockIdx.y * NPIX;
    #pragma unroll
    for (int i = 0; i < 8; i++) {
        int row = i * 32 + (t >> 4);
        int col = t & 15;
        sc[col * CSTRIDE + row] = plane[row * 256 + y0 + col];
    }
    __syncthreads();
    int lane = t & 127, grp = t >> 7;
    for (int j = 0; j < 4; j++)
        fft256(sc + (j * 4 + grp) * CSTRIDE, tw, lane);
    __syncthreads();
    #pragma unroll
    for (int i = 0; i < 8; i++) {
        int row = i * 32 + (t >> 4);
        int col = t & 15;
        plane[row * 256 + y0 + col] = sc[col * CSTRIDE + row];
    }
}

// ---------------------------------------------------------------------------
// Paired pointwise multiply + inverse FFT rows. grid=(64, 8), 512 thr.
// Pair p<7: H = fK[2p]*fA[2p%3] + i * fK[2p+1]*fA[(2p+1)%3];
// p==7:     H = fK[14]*fA[2].
// ifft2(H).re = U[2p], .im = U[2p+1] (real-output pairing, exact in exact
// arithmetic; fp32 adds ~1e-7 relative noise).
// ---------------------------------------------------------------------------
__global__ void __launch_bounds__(FFT_THREADS) k_inv_rows() {
    __shared__ float2 s[LPB][256];
    __shared__ float2 tw[128];
    fill_twiddles(tw, threadIdx.x, FFT_THREADS, 1.f);
    int lane = threadIdx.x & 127;
    int line = threadIdx.x >> 7;
    int x = blockIdx.x * LPB + line;
    int p = blockIdx.y;
    int k1 = 2 * p;
    float2* sl = s[line];
    if (p < 7) {
        int k2 = k1 + 1;
        int c1 = k1 % NCH, c2 = k2 % NCH;
        const float2* fa1 = d_fA + c1 * NPIX + x * 256;
        const float2* fa2 = d_fA + c2 * NPIX + x * 256;
        const float2* fk1 = d_fKT + k1 * NPIX + x * 256;
        const float2* fk2 = d_fKT + k2 * NPIX + x * 256;
        for (int y = lane; y < 256; y += 128) {
            float2 a1 = fa1[y], a2 = fa2[y];
            float2 q1 = fk1[y], q2 = fk2[y];
            float g1r = q1.x * a1.x - q1.y * a1.y;
            float g1i = q1.x * a1.y + q1.y * a1.x;
            float g2r = q2.x * a2.x - q2.y * a2.y;
            float g2i = q2.x * a2.y + q2.y * a2.x;
            sl[y] = make_float2(g1r - g2i, g1i + g2r);   // G1 + i*G2
        }
    } else {
        const float2* fa = d_fA + 2 * NPIX + x * 256;    // k=14 -> c=2
        const float2* fk = d_fKT + 14 * NPIX + x * 256;
        for (int y = lane; y < 256; y += 128) {
            float2 a = fa[y], q = fk[y];
            sl[y] = make_float2(q.x * a.x - q.y * a.y, q.x * a.y + q.y * a.x);
        }
    }
    __syncthreads();
    fft256(sl, tw, lane);
    float2* out = d_Gc + p * NPIX + x * 256;
    for (int y = lane; y < 256; y += 128) out[y] = sl[y];
}

// ---------------------------------------------------------------------------
// Inverse FFT columns (paired), 16-col tile; real->Ug[2p], imag->Ug[2p+1].
// grid=(16, 8), 512 thr.
// ---------------------------------------------------------------------------
__global__ void __launch_bounds__(512) k_inv_cols() {
    __shared__ float2 sc[TW * CSTRIDE];
    __shared__ float2 tw[128];
    fill_twiddles(tw, threadIdx.x, 512, 1.f);
    int t = threadIdx.x;
    int y0 = blockIdx.x * TW;
    int p = blockIdx.y;
    float2* plane = d_Gc + p * NPIX;
    #pragma unroll
    for (int i = 0; i < 8; i++) {
        int row = i * 32 + (t >> 4);
        int col = t & 15;
        sc[col * CSTRIDE + row] = plane[row * 256 + y0 + col];
    }
    __syncthreads();
    int lane = t & 127, grp = t >> 7;
    for (int j = 0; j < 4; j++)
        fft256(sc + (j * 4 + grp) * CSTRIDE, tw, lane);
    __syncthreads();
    int k1 = 2 * p;
    float* up1 = d_Ug + k1 * NPIX;
    if (p < 7) {
        float* up2 = d_Ug + (k1 + 1) * NPIX;
        #pragma unroll
        for (int i = 0; i < 8; i++) {
            int row = i * 32 + (t >> 4);
            int col = t & 15;
            float2 v = sc[col * CSTRIDE + row];
            up1[row * 256 + y0 + col] = v.x;
            up2[row * 256 + y0 + col] = v.y;
        }
    } else {
        #pragma unroll
        for (int i = 0; i < 8; i++) {
            int row = i * 32 + (t >> 4);
            int col = t & 15;
            up1[row * 256 + y0 + col] = sc[col * CSTRIDE + row].x;
        }
    }
}

// ---------------------------------------------------------------------------
// growth(U)*P + channel sum + Asum, all coalesced per pixel.
// ---------------------------------------------------------------------------
__global__ void __launch_bounds__(256) k_growchan(const float* __restrict__ A,
                                                  const float* __restrict__ P,
                                                  const float* __restrict__ mArr,
                                                  const float* __restrict__ sArr) {
    __shared__ float sm[NK], sinv[NK];
    if (threadIdx.x < NK) {
        float sk = sArr[threadIdx.x];
        sm[threadIdx.x]   = mArr[threadIdx.x];
        sinv[threadIdx.x] = 1.f / (2.f * sk * sk);
    }
    __syncthreads();
    int idx = blockIdx.x * 256 + threadIdx.x;
    float uc0 = 0.f, uc1 = 0.f, uc2 = 0.f;
    #pragma unroll
    for (int j = 0; j < 5; j++) {
        #pragma unroll
        for (int c = 0; c < NCH; c++) {
            int k = c + 3 * j;                 // same accumulation order as R11 k_chan
            float u = d_Ug[k * NPIX + idx] * (1.f / 65536.f);
            float d = u - sm[k];
            float g = 2.f * expf(-d * d * sinv[k]) - 1.f;
            float v = g * __ldg(&P[idx * NK + k]);
            if (c == 0) uc0 += v; else if (c == 1) uc1 += v; else uc2 += v;
        }
    }
    d_Uc[0 * NPIX + idx] = uc0;
    d_Uc[1 * NPIX + idx] = uc1;
    d_Uc[2 * NPIX + idx] = uc2;
    d_Asum[idx] = A[idx * 3] + A[idx * 3 + 1] + A[idx * 3 + 2];
}

// ---------------------------------------------------------------------------
// Sobel (true convolution, zero-padded 'same'), per plane
// ---------------------------------------------------------------------------
__device__ __forceinline__ void sobel_at(const float* __restrict__ p, int x, int y,
                                         float& g0, float& g1) {
    float v[3][3];
    #pragma unroll
    for (int i = -1; i <= 1; i++) {
        #pragma unroll
        for (int j = -1; j <= 1; j++) {
            int xx = x + i, yy = y + j;
            bool ok = (xx >= 0) && (xx < 256) && (yy >= 0) && (yy < 256);
            v[i + 1][j + 1] = ok ? p[xx * 256 + yy] : 0.f;
        }
    }
    g0 = (v[2][0] + 2.f * v[2][1] + v[2][2]) - (v[0][0] + 2.f * v[0][1] + v[0][2]);
    g1 = (v[0][2] + 2.f * v[1][2] + v[2][2]) - (v[0][0] + 2.f * v[1][0] + v[2][0]);
}

// Flow field + target centers (mus)
__global__ void __launch_bounds__(256) k_flow(const float* __restrict__ A) {
    int idx = blockIdx.x * 256 + threadIdx.x;
    int x = idx >> 8, y = idx & 255;
    float cg0, cg1;
    sobel_at(d_Asum, x, y, cg0, cg1);
    #pragma unroll
    for (int c = 0; c < NCH; c++) {
        float g0, g1;
        sobel_at(d_Uc + c * NPIX, x, y, g0, g1);
        float a = A[idx * 3 + c] * 0.5f;
        float alpha = fminf(a * a, 1.f);
        float F0 = fminf(fmaxf(g0 * (1.f - alpha) - cg0 * alpha, -MA_F), MA_F);
        float F1 = fminf(fmaxf(g1 * (1.f - alpha) - cg1 * alpha, -MA_F), MA_F);
        float mu0 = fminf(fmaxf((float)x + 0.5f + DT_F * F0, SIGMA_F), 256.f - SIGMA_F);
        float mu1 = fminf(fmaxf((float)y + 0.5f + DT_F * F1, SIGMA_F), 256.f - SIGMA_F);
        d_mus[idx * 6 + c]     = mu0;  // d = 0 (axis 0)
        d_mus[idx * 6 + 3 + c] = mu1;  // d = 1 (axis 1)
    }
}

// ---------------------------------------------------------------------------
// Reintegration gather (25-shift exact truncation; see prior rounds)
// ---------------------------------------------------------------------------
__global__ void __launch_bounds__(256) k_reint(const float* __restrict__ A,
                                               const float* __restrict__ P,
                                               float* __restrict__ out) {
    int idx = blockIdx.x * 256 + threadIdx.x;
    int x = idx >> 8, y = idx & 255;
    float px = (float)x + 0.5f, py = (float)y + 0.5f;
    const float invN = 1.f / (4.f * SIGMA_F * SIGMA_F);

    float nA0 = 0.f, nA1 = 0.f, nA2 = 0.f;
    float accP[NK];
    #pragma unroll
    for (int k = 0; k < NK; k++) accP[k] = 0.f;
    float wsum = 0.f;

    for (int dx = -2; dx <= 2; dx++) {
        int sx = (x - dx) & 255;
        for (int dy = -2; dy <= 2; dy++) {
            int sy = (y - dy) & 255;
            int sidx = sx * 256 + sy;
            const float* mu = d_mus + sidx * 6;

            float c0, c1, c2;
            {
                float f0 = fminf(fmaxf(0.5f + SIGMA_F - fabsf(px - __ldg(&mu[0])), 0.f), 1.f);
                float f1 = fminf(fmaxf(0.5f + SIGMA_F - fabsf(py - __ldg(&mu[3])), 0.f), 1.f);
                c0 = __ldg(&A[sidx * 3 + 0]) * (f0 * f1 * invN);
            }
            {
                float f0 = fminf(fmaxf(0.5f + SIGMA_F - fabsf(px - __ldg(&mu[1])), 0.f), 1.f);
                float f1 = fminf(fmaxf(0.5f + SIGMA_F - fabsf(py - __ldg(&mu[4])), 0.f), 1.f);
                c1 = __ldg(&A[sidx * 3 + 1]) * (f0 * f1 * invN);
            }
            {
                float f0 = fminf(fmaxf(0.5f + SIGMA_F - fabsf(px - __ldg(&mu[2])), 0.f), 1.f);
                float f1 = fminf(fmaxf(0.5f + SIGMA_F - fabsf(py - __ldg(&mu[5])), 0.f), 1.f);
                c2 = __ldg(&A[sidx * 3 + 2]) * (f0 * f1 * invN);
            }
            float s = c0 + c1 + c2;
            nA0 += c0; nA1 += c1; nA2 += c2;
            float e = expf(s) - 1.f;
            wsum += e;
            if (s != 0.f) {
                const float* Ps = P + sidx * NK;
                #pragma unroll
                for (int k = 0; k < NK; k++) accP[k] += __ldg(&Ps[k]) * e;
            }
        }
    }

    out[idx * 3 + 0] = nA0;
    out[idx * 3 + 1] = nA1;
    out[idx * 3 + 2] = nA2;
    float inv = 1.f / (wsum + 1e-10f);
    float* outP = out + NPIX * 3;
    #pragma unroll
    for (int k = 0; k < NK; k++) outP[idx * NK + k] = accP[k] * inv;
}

// ---------------------------------------------------------------------------
extern "C" void kernel_launch(void* const* d_in, const int* in_sizes, int n_in,
                              void* d_out, int out_size) {
    (void)in_sizes; (void)n_in; (void)out_size;
    const float* A   = (const float*)d_in[0];
    const float* P   = (const float*)d_in[1];
    const float* fKr = (const float*)d_in[2];
    const float* fKi = (const float*)d_in[3];
    const float* m   = (const float*)d_in[4];
    const float* s   = (const float*)d_in[5];
    float* out = (float*)d_out;

    k_tK<<<256, 256>>>(fKr, fKi);
    k_fwd_rows<<<dim3(256 / LPB, NCH), FFT_THREADS>>>(A);
    k_fwd_cols<<<dim3(256 / TW, NCH), 512>>>();
    k_inv_rows<<<dim3(256 / LPB, NPAIR), FFT_THREADS>>>();
    k_inv_cols<<<dim3(256 / TW, NPAIR), 512>>>();
    k_growchan<<<256, 256>>>(A, P, m, s);
    k_flow<<<256, 256>>>(A);
    k_reint<<<256, 256>>>(A, P, out);
}